// round 1
// baseline (speedup 1.0000x reference)
#include <cuda_runtime.h>
#include <cuda_bf16.h>

// AdaptiveLayer: out[b,t,f] = max(x[b,t,f] - adapt, 0); adapt = (adapt + 0.1*out)*0.9
// Serial along T, independent across B*F. HBM-streaming bound (512 MiB traffic).

#define AL_B 32
#define AL_T 512
#define AL_F 4096
#define AL_F4 (AL_F / 4)          // 1024 float4 per row
#define ADAPT_RATE 0.1f
#define ONE_MINUS_REC 0.9f

__global__ __launch_bounds__(128, 8)
void AdaptiveLayer_16252156248548_kernel(const float* __restrict__ x,
                                         const float* __restrict__ adaptation,
                                         float* __restrict__ out) {
    const int idx = blockIdx.x * blockDim.x + threadIdx.x;   // 0 .. B*F4-1
    const int b  = idx >> 10;        // idx / AL_F4
    const int f4 = idx & (AL_F4 - 1);

    const float4* __restrict__ xp =
        reinterpret_cast<const float4*>(x) + (size_t)b * AL_T * AL_F4 + f4;
    float4* __restrict__ op =
        reinterpret_cast<float4*>(out) + (size_t)b * AL_T * AL_F4 + f4;

    float4 a = reinterpret_cast<const float4*>(adaptation)[f4];

    // prefetch t=0
    float4 v = xp[0];

    #pragma unroll 4
    for (int t = 0; t < AL_T; ++t) {
        // issue next load early — independent of the adapt chain
        float4 vn;
        if (t + 1 < AL_T) vn = xp[(size_t)(t + 1) * AL_F4];

        float4 o;
        o.x = fmaxf(v.x - a.x, 0.0f);
        o.y = fmaxf(v.y - a.y, 0.0f);
        o.z = fmaxf(v.z - a.z, 0.0f);
        o.w = fmaxf(v.w - a.w, 0.0f);

        a.x = (fmaf(ADAPT_RATE, o.x, a.x)) * ONE_MINUS_REC;
        a.y = (fmaf(ADAPT_RATE, o.y, a.y)) * ONE_MINUS_REC;
        a.z = (fmaf(ADAPT_RATE, o.z, a.z)) * ONE_MINUS_REC;
        a.w = (fmaf(ADAPT_RATE, o.w, a.w)) * ONE_MINUS_REC;

        op[(size_t)t * AL_F4] = o;
        v = vn;
    }
}

extern "C" void kernel_launch(void* const* d_in, const int* in_sizes, int n_in,
                              void* d_out, int out_size) {
    const float* x          = (const float*)d_in[0];
    const float* adaptation = (const float*)d_in[1];
    float* out              = (float*)d_out;

    const int threads = AL_B * AL_F4;        // 32768
    const int block   = 128;
    const int grid    = threads / block;     // 256
    AdaptiveLayer_16252156248548_kernel<<<grid, block>>>(x, adaptation, out);
}

// round 2
// speedup vs baseline: 1.0161x; 1.0161x over previous
#include <cuda_runtime.h>
#include <cuda_bf16.h>

// AdaptiveLayer: out[b,t,f] = max(x[b,t,f] - adapt, 0); adapt = (adapt + 0.1*out)*0.9
// Serial along T (512), independent across B*F = 131072 chains (32768 float4 chains).
// Pure HBM stream: 256 MiB read + 256 MiB write. Round 2: fix CTA load imbalance
// (1024 x 32-thread CTAs) + software pipeline depth 4 for MLP.

#define AL_B 32
#define AL_T 512
#define AL_F 4096
#define AL_F4 (AL_F / 4)          // 1024 float4 per row
#define ADAPT_RATE 0.1f
#define ONE_MINUS_REC 0.9f
#define PIPE 4

__global__ __launch_bounds__(32, 24)
void AdaptiveLayer_16252156248548_kernel(const float* __restrict__ x,
                                         const float* __restrict__ adaptation,
                                         float* __restrict__ out) {
    const int idx = blockIdx.x * 32 + threadIdx.x;   // 0 .. B*F4-1
    const int b  = idx >> 10;        // idx / AL_F4
    const int f4 = idx & (AL_F4 - 1);

    const float4* __restrict__ xp =
        reinterpret_cast<const float4*>(x) + (size_t)b * AL_T * AL_F4 + f4;
    float4* __restrict__ op =
        reinterpret_cast<float4*>(out) + (size_t)b * AL_T * AL_F4 + f4;

    float4 a = __ldg(reinterpret_cast<const float4*>(adaptation) + f4);

    // Prime the pipeline: PIPE independent loads in flight.
    float4 buf[PIPE];
    #pragma unroll
    for (int i = 0; i < PIPE; ++i)
        buf[i] = __ldcs(xp + (size_t)i * AL_F4);

    #pragma unroll 4
    for (int t = 0; t < AL_T; ++t) {
        float4 v = buf[t & (PIPE - 1)];

        // Refill this slot with the load PIPE steps ahead (independent of the
        // adapt dependency chain) — keeps PIPE loads in flight.
        if (t + PIPE < AL_T)
            buf[t & (PIPE - 1)] = __ldcs(xp + (size_t)(t + PIPE) * AL_F4);

        float4 o;
        o.x = fmaxf(v.x - a.x, 0.0f);
        o.y = fmaxf(v.y - a.y, 0.0f);
        o.z = fmaxf(v.z - a.z, 0.0f);
        o.w = fmaxf(v.w - a.w, 0.0f);

        a.x = fmaf(ADAPT_RATE, o.x, a.x) * ONE_MINUS_REC;
        a.y = fmaf(ADAPT_RATE, o.y, a.y) * ONE_MINUS_REC;
        a.z = fmaf(ADAPT_RATE, o.z, a.z) * ONE_MINUS_REC;
        a.w = fmaf(ADAPT_RATE, o.w, a.w) * ONE_MINUS_REC;

        __stcs(op + (size_t)t * AL_F4, o);
    }
}

extern "C" void kernel_launch(void* const* d_in, const int* in_sizes, int n_in,
                              void* d_out, int out_size) {
    const float* x          = (const float*)d_in[0];
    const float* adaptation = (const float*)d_in[1];
    float* out              = (float*)d_out;

    const int total = AL_B * AL_F4;          // 32768 chains
    const int block = 32;                    // 1 warp per CTA -> fine-grain balance
    const int grid  = total / block;         // 1024 CTAs over 148 SMs (~6.9/SM)
    AdaptiveLayer_16252156248548_kernel<<<grid, block>>>(x, adaptation, out);
}